// round 1
// baseline (speedup 1.0000x reference)
#include <cuda_runtime.h>

#define B_   8
#define NF_  2048
#define NK_  4096
#define T_   6144
#define CIN_ 256
#define CKQ_ 64
#define COUT_ 256

// Scratch (static device arrays: allocation-free per harness rules)
__device__ float g_Q[(size_t)B_ * NF_ * CKQ_];    // 4 MB
__device__ float g_K[(size_t)B_ * NK_ * CKQ_];    // 8 MB
__device__ float g_V[(size_t)B_ * NK_ * COUT_];   // 32 MB

// ---------------------------------------------------------------------------
// Projection GEMM: Y[b*Mper + r][n] = sum_k X[b*T + base + r][k] * W[n][k] + bias[n]
// 64x64 output tile per block, 256 threads, 4x4 micro-tile, BK=16.
// ---------------------------------------------------------------------------
__global__ __launch_bounds__(256) void proj_kernel(
    const float* __restrict__ X, const float* __restrict__ W,
    const float* __restrict__ bias, float* __restrict__ Y,
    int Mper, int base, int N)
{
    __shared__ float As[16][64];
    __shared__ float Ws[16][64];
    const int t  = threadIdx.x;
    const int m0 = blockIdx.x * 64;
    const int n0 = blockIdx.y * 64;
    const int b  = m0 / Mper;
    const int r0 = m0 - b * Mper;
    const float* Xb = X + ((size_t)b * T_ + base + r0) * CIN_;
    const float* Wb = W + (size_t)n0 * CIN_;

    const int lm = t >> 2;          // 0..63
    const int lk = (t & 3) << 2;    // 0,4,8,12
    const int ty = t >> 4, tx = t & 15;

    float acc[4][4];
    #pragma unroll
    for (int i = 0; i < 4; i++)
        #pragma unroll
        for (int j = 0; j < 4; j++) acc[i][j] = 0.f;

    for (int kk = 0; kk < CIN_; kk += 16) {
        float4 av = *(const float4*)(Xb + (size_t)lm * CIN_ + kk + lk);
        float4 wv = *(const float4*)(Wb + (size_t)lm * CIN_ + kk + lk);
        __syncthreads();
        As[lk + 0][lm] = av.x; As[lk + 1][lm] = av.y;
        As[lk + 2][lm] = av.z; As[lk + 3][lm] = av.w;
        Ws[lk + 0][lm] = wv.x; Ws[lk + 1][lm] = wv.y;
        Ws[lk + 2][lm] = wv.z; Ws[lk + 3][lm] = wv.w;
        __syncthreads();
        #pragma unroll
        for (int k = 0; k < 16; k++) {
            float4 a = *(const float4*)&As[k][ty << 2];
            float4 w = *(const float4*)&Ws[k][tx << 2];
            float aa[4] = {a.x, a.y, a.z, a.w};
            float ww[4] = {w.x, w.y, w.z, w.w};
            #pragma unroll
            for (int i = 0; i < 4; i++)
                #pragma unroll
                for (int j = 0; j < 4; j++)
                    acc[i][j] += aa[i] * ww[j];
        }
    }

    float4 bv4 = *(const float4*)(bias + n0 + (tx << 2));
    float bb[4] = {bv4.x, bv4.y, bv4.z, bv4.w};
    #pragma unroll
    for (int i = 0; i < 4; i++) {
        float4 o = make_float4(acc[i][0] + bb[0], acc[i][1] + bb[1],
                               acc[i][2] + bb[2], acc[i][3] + bb[3]);
        *(float4*)(Y + ((size_t)b * Mper + r0 + (ty << 2) + i) * N + n0 + (tx << 2)) = o;
    }
}

// ---------------------------------------------------------------------------
// Keep-row passthrough: out rows [b*T+NF, b*T+T) = features rows (same index)
// ---------------------------------------------------------------------------
__global__ void copy_keep(const float4* __restrict__ f, float4* __restrict__ o)
{
    const int per = NK_ * (COUT_ / 4);  // float4 per batch keep region
    const size_t total = (size_t)B_ * per;
    for (size_t i = blockIdx.x * (size_t)blockDim.x + threadIdx.x; i < total;
         i += (size_t)gridDim.x * blockDim.x) {
        size_t b = i / per;
        size_t r = i - b * per;
        size_t idx = ((size_t)b * T_ + NF_) * (COUT_ / 4) + r;
        o[idx] = f[idx];
    }
}

// ---------------------------------------------------------------------------
// Flash attention: one CTA = 64 fill rows of one batch. 64-key tiles.
// smem: Qs[d][i] 16KB, Ks[d][j] 16KB, Ps[i][j] (stride 65) 16.25KB,
//       Vs[j][c] 64KB, row stats. ~113KB dynamic.
// Thread micro-tile for PV: 4 rows x 16 cols (4 float4 groups strided by 64).
// ---------------------------------------------------------------------------
#define PS_STR 65
#define ATTN_SMEM_FLOATS (4096 + 4096 + 64 * PS_STR + 64 * 256 + 192)

__global__ __launch_bounds__(256, 1) void attn_kernel(
    const float* __restrict__ Q, const float* __restrict__ K,
    const float* __restrict__ V, float* __restrict__ out)
{
    extern __shared__ float sm[];
    float* Qs   = sm;                        // [64][64] d-major
    float* Ks   = Qs + 4096;                 // [64][64] d-major
    float* Ps   = Ks + 4096;                 // [64][PS_STR]
    float* Vs   = Ps + 64 * PS_STR;          // [64][256]
    float* sm_m = Vs + 64 * 256;
    float* sm_l = sm_m + 64;
    float* sm_sc = sm_l + 64;

    const int t  = threadIdx.x;
    const int b  = blockIdx.y;
    const int mt = blockIdx.x;
    const float*  Qb = Q + ((size_t)b * NF_ + mt * 64) * 64;
    const float*  Kb = K + (size_t)b * NK_ * 64;
    const float4* Vb = (const float4*)(V + (size_t)b * NK_ * 256);

    // Load Q tile (prescaled by 1/sqrt(64))
    {
        int i = t >> 2, d4 = (t & 3) << 2;
        #pragma unroll
        for (int dd = 0; dd < 64; dd += 16) {
            float4 v = *(const float4*)(Qb + (size_t)i * 64 + dd + d4);
            Qs[(dd + d4 + 0) * 64 + i] = v.x * 0.125f;
            Qs[(dd + d4 + 1) * 64 + i] = v.y * 0.125f;
            Qs[(dd + d4 + 2) * 64 + i] = v.z * 0.125f;
            Qs[(dd + d4 + 3) * 64 + i] = v.w * 0.125f;
        }
    }
    if (t < 64) { sm_m[t] = -1e30f; sm_l[t] = 0.f; }

    const int tr = t >> 4, tc = t & 15;
    const int r0 = tr << 2;

    float acc[4][4][4];
    #pragma unroll
    for (int i = 0; i < 4; i++)
        #pragma unroll
        for (int k = 0; k < 4; k++)
            #pragma unroll
            for (int c = 0; c < 4; c++) acc[i][k][c] = 0.f;

    for (int kt = 0; kt < NK_ / 64; kt++) {
        __syncthreads();  // prev PV done before overwriting Ks/Vs
        {   // load K tile (d-major)
            int j = t >> 2, d4 = (t & 3) << 2;
            #pragma unroll
            for (int dd = 0; dd < 64; dd += 16) {
                float4 v = *(const float4*)(Kb + (size_t)(kt * 64 + j) * 64 + dd + d4);
                Ks[(dd + d4 + 0) * 64 + j] = v.x;
                Ks[(dd + d4 + 1) * 64 + j] = v.y;
                Ks[(dd + d4 + 2) * 64 + j] = v.z;
                Ks[(dd + d4 + 3) * 64 + j] = v.w;
            }
        }
        {   // load V tile [64][256] row-major
            #pragma unroll
            for (int w = 0; w < 16; w++) {
                int g = w * 256 + t;
                int j = g >> 6, c = g & 63;
                ((float4*)Vs)[j * 64 + c] = Vb[(size_t)(kt * 64 + j) * 64 + c];
            }
        }
        __syncthreads();

        // S = Q K^T  (4x4 micro-tile)
        float sreg[4][4];
        #pragma unroll
        for (int i = 0; i < 4; i++)
            #pragma unroll
            for (int j = 0; j < 4; j++) sreg[i][j] = 0.f;
        #pragma unroll 8
        for (int d = 0; d < 64; d++) {
            float4 q = *(const float4*)&Qs[d * 64 + r0];
            float4 k = *(const float4*)&Ks[d * 64 + (tc << 2)];
            float qq[4] = {q.x, q.y, q.z, q.w};
            float kk[4] = {k.x, k.y, k.z, k.w};
            #pragma unroll
            for (int i = 0; i < 4; i++)
                #pragma unroll
                for (int j = 0; j < 4; j++)
                    sreg[i][j] += qq[i] * kk[j];
        }
        #pragma unroll
        for (int i = 0; i < 4; i++)
            #pragma unroll
            for (int j = 0; j < 4; j++)
                Ps[(r0 + i) * PS_STR + (tc << 2) + j] = sreg[i][j];
        __syncthreads();

        // online softmax: 4 threads per row
        {
            int r = t >> 2, q = t & 3;
            float* row = Ps + r * PS_STR + q * 16;
            float mx = row[0];
            #pragma unroll
            for (int j = 1; j < 16; j++) mx = fmaxf(mx, row[j]);
            mx = fmaxf(mx, __shfl_xor_sync(0xffffffffu, mx, 1));
            mx = fmaxf(mx, __shfl_xor_sync(0xffffffffu, mx, 2));
            float m_old = sm_m[r];
            float m_new = fmaxf(m_old, mx);
            float ssum = 0.f;
            #pragma unroll
            for (int j = 0; j < 16; j++) {
                float p = __expf(row[j] - m_new);
                row[j] = p;
                ssum += p;
            }
            ssum += __shfl_xor_sync(0xffffffffu, ssum, 1);
            ssum += __shfl_xor_sync(0xffffffffu, ssum, 2);
            if (q == 0) {
                float scale = __expf(m_old - m_new);
                sm_sc[r] = scale;
                sm_l[r] = sm_l[r] * scale + ssum;
                sm_m[r] = m_new;
            }
        }
        __syncthreads();

        // rescale O and accumulate P @ V
        {
            float sc[4];
            #pragma unroll
            for (int i = 0; i < 4; i++) sc[i] = sm_sc[r0 + i];
            #pragma unroll
            for (int i = 0; i < 4; i++)
                #pragma unroll
                for (int k = 0; k < 4; k++)
                    #pragma unroll
                    for (int c = 0; c < 4; c++) acc[i][k][c] *= sc[i];

            #pragma unroll 4
            for (int j = 0; j < 64; j++) {
                float pp[4];
                #pragma unroll
                for (int i = 0; i < 4; i++) pp[i] = Ps[(r0 + i) * PS_STR + j];
                #pragma unroll
                for (int k = 0; k < 4; k++) {
                    float4 v4 = *(const float4*)&Vs[j * 256 + k * 64 + (tc << 2)];
                    float vv[4] = {v4.x, v4.y, v4.z, v4.w};
                    #pragma unroll
                    for (int i = 0; i < 4; i++)
                        #pragma unroll
                        for (int c = 0; c < 4; c++)
                            acc[i][k][c] += pp[i] * vv[c];
                }
            }
        }
    }

    // epilogue: O / l, write fill rows
    #pragma unroll
    for (int i = 0; i < 4; i++) {
        float invi = 1.f / sm_l[r0 + i];
        #pragma unroll
        for (int k = 0; k < 4; k++) {
            float4 o = make_float4(acc[i][k][0] * invi, acc[i][k][1] * invi,
                                   acc[i][k][2] * invi, acc[i][k][3] * invi);
            *(float4*)(out + ((size_t)b * T_ + mt * 64 + r0 + i) * 256 +
                       k * 64 + (tc << 2)) = o;
        }
    }
}

// ---------------------------------------------------------------------------
extern "C" void kernel_launch(void* const* d_in, const int* in_sizes, int n_in,
                              void* d_out, int out_size)
{
    (void)in_sizes; (void)n_in; (void)out_size;
    const float* features = (const float*)d_in[0];
    // d_in[1] = keep_flag (unused)
    const float* Wq = (const float*)d_in[2];
    const float* bq = (const float*)d_in[3];
    const float* Wk = (const float*)d_in[4];
    const float* bk = (const float*)d_in[5];
    const float* Wv = (const float*)d_in[6];
    const float* bv = (const float*)d_in[7];
    float* out = (float*)d_out;

    float *qp, *kp, *vp;
    cudaGetSymbolAddress((void**)&qp, g_Q);
    cudaGetSymbolAddress((void**)&kp, g_K);
    cudaGetSymbolAddress((void**)&vp, g_V);

    // Projections
    proj_kernel<<<dim3((B_ * NF_) / 64, 1), 256>>>(features, Wq, bq, qp, NF_, 0, CKQ_);
    proj_kernel<<<dim3((B_ * NK_) / 64, 1), 256>>>(features, Wk, bk, kp, NK_, NF_, CKQ_);
    proj_kernel<<<dim3((B_ * NK_) / 64, COUT_ / 64), 256>>>(features, Wv, bv, vp, NK_, NF_, COUT_);

    // Passthrough of keep rows
    copy_keep<<<2048, 256>>>((const float4*)features, (float4*)out);

    // Flash attention over fill rows
    size_t smem = ATTN_SMEM_FLOATS * sizeof(float);
    cudaFuncSetAttribute(attn_kernel, cudaFuncAttributeMaxDynamicSharedMemorySize, (int)smem);
    attn_kernel<<<dim3(NF_ / 64, B_), 256, smem>>>(qp, kp, vp, out);
}

// round 2
// speedup vs baseline: 3.9058x; 3.9058x over previous
#include <cuda_runtime.h>
#include <cuda_bf16.h>
#include <cstdint>

#define B_   8
#define NF_  2048
#define NK_  4096
#define T_   6144
#define CIN_ 256
#define CKQ_ 64
#define COUT_ 256

typedef __nv_bfloat16 bf16;

// bf16 scratch (static device arrays: allocation-free per harness rules)
__device__ __align__(256) bf16 g_Q[(size_t)B_ * NF_ * CKQ_];    // 2 MB (prescaled by 1/8)
__device__ __align__(256) bf16 g_K[(size_t)B_ * NK_ * CKQ_];    // 4 MB
__device__ __align__(256) bf16 g_V[(size_t)B_ * NK_ * COUT_];   // 16 MB

// ---------------------------------------------------------------------------
// PTX helpers
// ---------------------------------------------------------------------------
__device__ __forceinline__ uint32_t smem_u32(const void* p) {
    return (uint32_t)__cvta_generic_to_shared(p);
}
__device__ __forceinline__ void cp16(bf16* dst, const bf16* src) {
    asm volatile("cp.async.cg.shared.global [%0], [%1], 16;\n"
                 :: "r"(smem_u32(dst)), "l"(src));
}
__device__ __forceinline__ void ldsm4(uint32_t& a0, uint32_t& a1, uint32_t& a2,
                                      uint32_t& a3, uint32_t addr) {
    asm volatile("ldmatrix.sync.aligned.m8n8.x4.shared.b16 {%0,%1,%2,%3}, [%4];\n"
                 : "=r"(a0), "=r"(a1), "=r"(a2), "=r"(a3) : "r"(addr));
}
__device__ __forceinline__ void ldsm4t(uint32_t& a0, uint32_t& a1, uint32_t& a2,
                                       uint32_t& a3, uint32_t addr) {
    asm volatile("ldmatrix.sync.aligned.m8n8.x4.trans.shared.b16 {%0,%1,%2,%3}, [%4];\n"
                 : "=r"(a0), "=r"(a1), "=r"(a2), "=r"(a3) : "r"(addr));
}
__device__ __forceinline__ void mma16816(float* c, uint32_t a0, uint32_t a1,
                                         uint32_t a2, uint32_t a3,
                                         uint32_t b0, uint32_t b1) {
    asm volatile("mma.sync.aligned.m16n8k16.row.col.f32.bf16.bf16.f32 "
                 "{%0,%1,%2,%3}, {%4,%5,%6,%7}, {%8,%9}, {%0,%1,%2,%3};\n"
                 : "+f"(c[0]), "+f"(c[1]), "+f"(c[2]), "+f"(c[3])
                 : "r"(a0), "r"(a1), "r"(a2), "r"(a3), "r"(b0), "r"(b1));
}

// ---------------------------------------------------------------------------
// Projection GEMM (fp32 compute, bf16 output with scale):
// Y[b*Mper + r][n] = (sum_k X[b*T + base + r][k] * W[n][k] + bias[n]) * scale
// 64x64 tile per block, 256 threads, 4x4 micro-tile, BK=16.
// ---------------------------------------------------------------------------
__global__ __launch_bounds__(256) void proj_kernel(
    const float* __restrict__ X, const float* __restrict__ W,
    const float* __restrict__ bias, bf16* __restrict__ Y,
    int Mper, int base, int N, float scale)
{
    __shared__ float As[16][64];
    __shared__ float Ws[16][64];
    const int t  = threadIdx.x;
    const int m0 = blockIdx.x * 64;
    const int n0 = blockIdx.y * 64;
    const int b  = m0 / Mper;
    const int r0 = m0 - b * Mper;
    const float* Xb = X + ((size_t)b * T_ + base + r0) * CIN_;
    const float* Wb = W + (size_t)n0 * CIN_;

    const int lm = t >> 2;          // 0..63
    const int lk = (t & 3) << 2;    // 0,4,8,12
    const int ty = t >> 4, tx = t & 15;

    float acc[4][4];
    #pragma unroll
    for (int i = 0; i < 4; i++)
        #pragma unroll
        for (int j = 0; j < 4; j++) acc[i][j] = 0.f;

    for (int kk = 0; kk < CIN_; kk += 16) {
        float4 av = *(const float4*)(Xb + (size_t)lm * CIN_ + kk + lk);
        float4 wv = *(const float4*)(Wb + (size_t)lm * CIN_ + kk + lk);
        __syncthreads();
        As[lk + 0][lm] = av.x; As[lk + 1][lm] = av.y;
        As[lk + 2][lm] = av.z; As[lk + 3][lm] = av.w;
        Ws[lk + 0][lm] = wv.x; Ws[lk + 1][lm] = wv.y;
        Ws[lk + 2][lm] = wv.z; Ws[lk + 3][lm] = wv.w;
        __syncthreads();
        #pragma unroll
        for (int k = 0; k < 16; k++) {
            float4 a = *(const float4*)&As[k][ty << 2];
            float4 w = *(const float4*)&Ws[k][tx << 2];
            float aa[4] = {a.x, a.y, a.z, a.w};
            float ww[4] = {w.x, w.y, w.z, w.w};
            #pragma unroll
            for (int i = 0; i < 4; i++)
                #pragma unroll
                for (int j = 0; j < 4; j++)
                    acc[i][j] += aa[i] * ww[j];
        }
    }

    float4 bv4 = *(const float4*)(bias + n0 + (tx << 2));
    float bb[4] = {bv4.x, bv4.y, bv4.z, bv4.w};
    #pragma unroll
    for (int i = 0; i < 4; i++) {
        float v0 = (acc[i][0] + bb[0]) * scale;
        float v1 = (acc[i][1] + bb[1]) * scale;
        float v2 = (acc[i][2] + bb[2]) * scale;
        float v3 = (acc[i][3] + bb[3]) * scale;
        __nv_bfloat162 h01 = __floats2bfloat162_rn(v0, v1);
        __nv_bfloat162 h23 = __floats2bfloat162_rn(v2, v3);
        uint2 u;
        u.x = *reinterpret_cast<uint32_t*>(&h01);
        u.y = *reinterpret_cast<uint32_t*>(&h23);
        *(uint2*)(Y + ((size_t)b * Mper + r0 + (ty << 2) + i) * N + n0 + (tx << 2)) = u;
    }
}

// ---------------------------------------------------------------------------
// Keep-row passthrough (fp32, exact)
// ---------------------------------------------------------------------------
__global__ void copy_keep(const float4* __restrict__ f, float4* __restrict__ o)
{
    const int per = NK_ * (COUT_ / 4);
    const size_t total = (size_t)B_ * per;
    for (size_t i = blockIdx.x * (size_t)blockDim.x + threadIdx.x; i < total;
         i += (size_t)gridDim.x * blockDim.x) {
        size_t b = i / per;
        size_t r = i - b * per;
        size_t idx = ((size_t)b * T_ + NF_) * (COUT_ / 4) + r;
        o[idx] = f[idx];
    }
}

// ---------------------------------------------------------------------------
// Flash attention (bf16 mma.sync): CTA = 128 fill rows, Bc = 64 keys/tile.
// 8 warps, warp w owns rows 16w..16w+15, full dv=256 in registers.
// smem: Qs[128][72], Ks[2][64][72], Vs[2][64][264] bf16 = 104448 B.
// ---------------------------------------------------------------------------
#define QS_OFF   0
#define KS_OFF   9216            // 128*72
#define VS_OFF   18432           // + 2*64*72
#define ATTN_SMEM_BYTES (104448) // (18432 + 2*4608 + 2*16896) elems * 2

__global__ __launch_bounds__(256) void attn_kernel(
    const bf16* __restrict__ Q, const bf16* __restrict__ K,
    const bf16* __restrict__ V, float* __restrict__ out)
{
    extern __shared__ bf16 smx[];
    bf16* Qs  = smx + QS_OFF;
    bf16* Ksb = smx + KS_OFF;
    bf16* Vsb = smx + VS_OFF;

    const int t = threadIdx.x;
    const int w = t >> 5, lane = t & 31;
    const int b = blockIdx.y, mt = blockIdx.x;

    const bf16* Qg = Q + ((size_t)b * NF_ + mt * 128) * 64;
    const bf16* Kg = K + (size_t)b * NK_ * 64;
    const bf16* Vg = V + (size_t)b * NK_ * 256;

    // group: Q tile (128 rows x 128B)
    #pragma unroll
    for (int i = 0; i < 4; i++) {
        int c = t + i * 256;
        int row = c >> 3, ch = c & 7;
        cp16(Qs + row * 72 + ch * 8, Qg + row * 64 + ch * 8);
    }
    asm volatile("cp.async.commit_group;\n");

    // group: tile 0 K/V into buffer 0
    #pragma unroll
    for (int i = 0; i < 2; i++) {
        int c = t + i * 256; int row = c >> 3, ch = c & 7;
        cp16(Ksb + row * 72 + ch * 8, Kg + row * 64 + ch * 8);
    }
    #pragma unroll
    for (int i = 0; i < 8; i++) {
        int c = t + i * 256; int row = c >> 5, ch = c & 31;
        cp16(Vsb + row * 264 + ch * 8, Vg + row * 256 + ch * 8);
    }
    asm volatile("cp.async.commit_group;\n");

    float o[32][4];
    #pragma unroll
    for (int n = 0; n < 32; n++) { o[n][0]=0.f; o[n][1]=0.f; o[n][2]=0.f; o[n][3]=0.f; }
    float m0 = -1e30f, m1 = -1e30f, l0 = 0.f, l1 = 0.f;

    const uint32_t qaddr = smem_u32(Qs + (w * 16 + (lane & 15)) * 72 + ((lane >> 4) << 3));
    const int k_row16 = ((lane >> 4) << 3) + (lane & 7);
    const int k_col8  = ((lane >> 3) & 1) << 3;
    const int v_row   = lane & 15;
    const int v_col8  = (lane >> 4) << 3;

    for (int kt = 0; kt < 64; kt++) {
        __syncthreads();   // all warps done with buffer (kt+1)&1 (tile kt-1)
        if (kt + 1 < 64) {
            int buf = (kt + 1) & 1;
            const bf16* Kt = Kg + (size_t)(kt + 1) * 64 * 64;
            const bf16* Vt = Vg + (size_t)(kt + 1) * 64 * 256;
            bf16* Kd = Ksb + buf * 4608;
            bf16* Vd = Vsb + buf * 16896;
            #pragma unroll
            for (int i = 0; i < 2; i++) {
                int c = t + i * 256; int row = c >> 3, ch = c & 7;
                cp16(Kd + row * 72 + ch * 8, Kt + row * 64 + ch * 8);
            }
            #pragma unroll
            for (int i = 0; i < 8; i++) {
                int c = t + i * 256; int row = c >> 5, ch = c & 31;
                cp16(Vd + row * 264 + ch * 8, Vt + row * 256 + ch * 8);
            }
        }
        asm volatile("cp.async.commit_group;\n");
        asm volatile("cp.async.wait_group 1;\n");
        __syncthreads();

        const int cur = kt & 1;
        const uint32_t kbase = smem_u32(Ksb + cur * 4608);
        const uint32_t vbase = smem_u32(Vsb + cur * 16896);

        // ---- S = Q K^T (Q prescaled by 1/8) ----
        float s[8][4];
        #pragma unroll
        for (int j = 0; j < 8; j++) { s[j][0]=0.f; s[j][1]=0.f; s[j][2]=0.f; s[j][3]=0.f; }
        #pragma unroll
        for (int ks = 0; ks < 4; ks++) {
            uint32_t a0, a1, a2, a3;
            ldsm4(a0, a1, a2, a3, qaddr + ks * 32);
            #pragma unroll
            for (int jp = 0; jp < 4; jp++) {
                uint32_t b0, b1, b2, b3;
                ldsm4(b0, b1, b2, b3,
                      kbase + (uint32_t)(((16 * jp + k_row16) * 72 + ks * 16 + k_col8) * 2));
                mma16816(s[2 * jp],     a0, a1, a2, a3, b0, b1);
                mma16816(s[2 * jp + 1], a0, a1, a2, a3, b2, b3);
            }
        }

        // ---- online softmax (registers only) ----
        float mx0 = -1e30f, mx1 = -1e30f;
        #pragma unroll
        for (int j = 0; j < 8; j++) {
            mx0 = fmaxf(mx0, fmaxf(s[j][0], s[j][1]));
            mx1 = fmaxf(mx1, fmaxf(s[j][2], s[j][3]));
        }
        mx0 = fmaxf(mx0, __shfl_xor_sync(0xffffffffu, mx0, 1));
        mx0 = fmaxf(mx0, __shfl_xor_sync(0xffffffffu, mx0, 2));
        mx1 = fmaxf(mx1, __shfl_xor_sync(0xffffffffu, mx1, 1));
        mx1 = fmaxf(mx1, __shfl_xor_sync(0xffffffffu, mx1, 2));
        float mn0 = fmaxf(m0, mx0), mn1 = fmaxf(m1, mx1);
        float c0 = __expf(m0 - mn0), c1 = __expf(m1 - mn1);
        m0 = mn0; m1 = mn1;

        float rs0 = 0.f, rs1 = 0.f;
        uint32_t p[16];
        #pragma unroll
        for (int j = 0; j < 8; j++) {
            float p0 = __expf(s[j][0] - mn0), p1 = __expf(s[j][1] - mn0);
            float p2 = __expf(s[j][2] - mn1), p3 = __expf(s[j][3] - mn1);
            rs0 += p0 + p1; rs1 += p2 + p3;
            __nv_bfloat162 h0 = __floats2bfloat162_rn(p0, p1);
            __nv_bfloat162 h1 = __floats2bfloat162_rn(p2, p3);
            p[2 * j]     = *reinterpret_cast<uint32_t*>(&h0);
            p[2 * j + 1] = *reinterpret_cast<uint32_t*>(&h1);
        }
        rs0 += __shfl_xor_sync(0xffffffffu, rs0, 1);
        rs0 += __shfl_xor_sync(0xffffffffu, rs0, 2);
        rs1 += __shfl_xor_sync(0xffffffffu, rs1, 1);
        rs1 += __shfl_xor_sync(0xffffffffu, rs1, 2);
        l0 = l0 * c0 + rs0;
        l1 = l1 * c1 + rs1;

        #pragma unroll
        for (int n = 0; n < 32; n++) {
            o[n][0] *= c0; o[n][1] *= c0; o[n][2] *= c1; o[n][3] *= c1;
        }

        // ---- O += P V ----
        #pragma unroll
        for (int kf = 0; kf < 4; kf++) {
            uint32_t pa0 = p[4 * kf + 0], pa1 = p[4 * kf + 1];
            uint32_t pa2 = p[4 * kf + 2], pa3 = p[4 * kf + 3];
            #pragma unroll
            for (int np = 0; np < 16; np++) {
                uint32_t b0, b1, b2, b3;
                ldsm4t(b0, b1, b2, b3,
                       vbase + (uint32_t)(((kf * 16 + v_row) * 264 + np * 16 + v_col8) * 2));
                mma16816(o[2 * np],     pa0, pa1, pa2, pa3, b0, b1);
                mma16816(o[2 * np + 1], pa0, pa1, pa2, pa3, b2, b3);
            }
        }
    }

    // ---- epilogue ----
    const float inv0 = 1.f / l0, inv1 = 1.f / l1;
    const int r = lane >> 2, qr = lane & 3;
    const size_t row0 = (size_t)b * T_ + mt * 128 + w * 16 + r;
    float* o0 = out + row0 * 256 + qr * 2;
    float* o1 = out + (row0 + 8) * 256 + qr * 2;
    #pragma unroll
    for (int n = 0; n < 32; n++) {
        *(float2*)(o0 + n * 8) = make_float2(o[n][0] * inv0, o[n][1] * inv0);
        *(float2*)(o1 + n * 8) = make_float2(o[n][2] * inv1, o[n][3] * inv1);
    }
}

// ---------------------------------------------------------------------------
extern "C" void kernel_launch(void* const* d_in, const int* in_sizes, int n_in,
                              void* d_out, int out_size)
{
    (void)in_sizes; (void)n_in; (void)out_size;
    const float* features = (const float*)d_in[0];
    const float* Wq = (const float*)d_in[2];
    const float* bq = (const float*)d_in[3];
    const float* Wk = (const float*)d_in[4];
    const float* bk = (const float*)d_in[5];
    const float* Wv = (const float*)d_in[6];
    const float* bv = (const float*)d_in[7];
    float* out = (float*)d_out;

    bf16 *qp, *kp, *vp;
    cudaGetSymbolAddress((void**)&qp, g_Q);
    cudaGetSymbolAddress((void**)&kp, g_K);
    cudaGetSymbolAddress((void**)&vp, g_V);

    // Projections (Q prescaled by 1/sqrt(64) = 0.125, exact power of 2)
    proj_kernel<<<dim3((B_ * NF_) / 64, 1), 256>>>(features, Wq, bq, qp, NF_, 0, CKQ_, 0.125f);
    proj_kernel<<<dim3((B_ * NK_) / 64, 1), 256>>>(features, Wk, bk, kp, NK_, NF_, CKQ_, 1.f);
    proj_kernel<<<dim3((B_ * NK_) / 64, COUT_ / 64), 256>>>(features, Wv, bv, vp, NK_, NF_, COUT_, 1.f);

    // Passthrough of keep rows
    copy_keep<<<2048, 256>>>((const float4*)features, (float4*)out);

    // Flash attention over fill rows
    cudaFuncSetAttribute(attn_kernel, cudaFuncAttributeMaxDynamicSharedMemorySize,
                         ATTN_SMEM_BYTES);
    attn_kernel<<<dim3(NF_ / 128, B_), 256, ATTN_SMEM_BYTES>>>(qp, kp, vp, out);
}

// round 6
// speedup vs baseline: 6.4137x; 1.6421x over previous
#include <cuda_runtime.h>
#include <cuda_bf16.h>
#include <cstdint>

#define B_   8
#define NF_  2048
#define NK_  4096
#define T_   6144
#define CIN_ 256
#define CKQ_ 64
#define COUT_ 256

typedef __nv_bfloat16 bf16;

// bf16 scratch (static device arrays: allocation-free per harness rules)
__device__ __align__(256) bf16 g_Q[(size_t)B_ * NF_ * CKQ_];    // 2 MB (prescaled 1/8)
__device__ __align__(256) bf16 g_K[(size_t)B_ * NK_ * CKQ_];    // 4 MB
__device__ __align__(256) bf16 g_V[(size_t)B_ * NK_ * COUT_];   // 16 MB
__device__ __align__(256) bf16 g_Fb[(size_t)B_ * T_ * CIN_];    // 25 MB features bf16
__device__ __align__(256) bf16 g_Wq[CKQ_ * CIN_];
__device__ __align__(256) bf16 g_Wk[CKQ_ * CIN_];
__device__ __align__(256) bf16 g_Wv[COUT_ * CIN_];

// ---------------------------------------------------------------------------
// PTX helpers
// ---------------------------------------------------------------------------
__device__ __forceinline__ uint32_t smem_u32(const void* p) {
    return (uint32_t)__cvta_generic_to_shared(p);
}
__device__ __forceinline__ void cp16(bf16* dst, const bf16* src) {
    asm volatile("cp.async.cg.shared.global [%0], [%1], 16;\n"
                 :: "r"(smem_u32(dst)), "l"(src));
}
__device__ __forceinline__ void ldsm4(uint32_t& a0, uint32_t& a1, uint32_t& a2,
                                      uint32_t& a3, uint32_t addr) {
    asm volatile("ldmatrix.sync.aligned.m8n8.x4.shared.b16 {%0,%1,%2,%3}, [%4];\n"
                 : "=r"(a0), "=r"(a1), "=r"(a2), "=r"(a3) : "r"(addr));
}
__device__ __forceinline__ void ldsm4t(uint32_t& a0, uint32_t& a1, uint32_t& a2,
                                       uint32_t& a3, uint32_t addr) {
    asm volatile("ldmatrix.sync.aligned.m8n8.x4.trans.shared.b16 {%0,%1,%2,%3}, [%4];\n"
                 : "=r"(a0), "=r"(a1), "=r"(a2), "=r"(a3) : "r"(addr));
}
__device__ __forceinline__ void mma16816(float* c, uint32_t a0, uint32_t a1,
                                         uint32_t a2, uint32_t a3,
                                         uint32_t b0, uint32_t b1) {
    asm volatile("mma.sync.aligned.m16n8k16.row.col.f32.bf16.bf16.f32 "
                 "{%0,%1,%2,%3}, {%4,%5,%6,%7}, {%8,%9}, {%0,%1,%2,%3};\n"
                 : "+f"(c[0]), "+f"(c[1]), "+f"(c[2]), "+f"(c[3])
                 : "r"(a0), "r"(a1), "r"(a2), "r"(a3), "r"(b0), "r"(b1));
}
__device__ __forceinline__ uint32_t bf2u(float a, float b) {
    __nv_bfloat162 h = __floats2bfloat162_rn(a, b);
    return *reinterpret_cast<uint32_t*>(&h);
}

// ---------------------------------------------------------------------------
// fp32 -> bf16 conversion (vectorized, grid-stride)
// ---------------------------------------------------------------------------
__global__ void f2bf(const float4* __restrict__ in, uint2* __restrict__ out, long n4)
{
    for (long i = blockIdx.x * (long)blockDim.x + threadIdx.x; i < n4;
         i += (long)gridDim.x * blockDim.x) {
        float4 v = in[i];
        out[i] = make_uint2(bf2u(v.x, v.y), bf2u(v.z, v.w));
    }
}

// ---------------------------------------------------------------------------
// Projection GEMM on tensor cores (bf16 in, fp32 accum, bf16 out):
// Y[b*Mper + r][n0+n] = (sum_k Fb[b*T + base + r][k] * W[n0+n][k] + bias) * scale
// CTA tile 128 x NT, 8 warps (warp w = rows 16w..16w+15, all NT cols),
// K chunks of 64, cp.async double-buffered.
// ---------------------------------------------------------------------------
template <int NT>
__global__ __launch_bounds__(256) void proj_mma(
    const bf16* __restrict__ Fb, const bf16* __restrict__ W,
    const float* __restrict__ bias, bf16* __restrict__ Y,
    int Mper, int base, int Ntot, float scale)
{
    extern __shared__ bf16 smx[];
    const int BUF = 128 * 72 + NT * 72;     // elems per buffer
    bf16* As = smx;                          // [128][72] (+ buf*BUF)
    bf16* Bs = smx + 128 * 72;

    const int t = threadIdx.x;
    const int w = t >> 5, lane = t & 31;
    const int m0 = blockIdx.x * 128;
    const int n0 = blockIdx.y * NT;
    const int b  = m0 / Mper;
    const int r0 = m0 - b * Mper;
    const bf16* Ag = Fb + ((size_t)b * T_ + base + r0) * CIN_;
    const bf16* Wg = W + (size_t)n0 * CIN_;

    // prologue: chunk 0
    {
        #pragma unroll
        for (int i = 0; i < 4; i++) {
            int c = t + i * 256; int row = c >> 3, ch = c & 7;
            cp16(As + row * 72 + ch * 8, Ag + (size_t)row * CIN_ + ch * 8);
        }
        #pragma unroll
        for (int i = 0; i < NT / 32; i++) {
            int c = t + i * 256; int row = c >> 3, ch = c & 7;
            cp16(Bs + row * 72 + ch * 8, Wg + (size_t)row * CIN_ + ch * 8);
        }
        asm volatile("cp.async.commit_group;\n");
    }

    float acc[2 * (NT / 16)][4];
    #pragma unroll
    for (int j = 0; j < 2 * (NT / 16); j++) {
        acc[j][0] = 0.f; acc[j][1] = 0.f; acc[j][2] = 0.f; acc[j][3] = 0.f;
    }

    const uint32_t a_off = (uint32_t)(((w * 16 + (lane & 15)) * 72 + ((lane >> 4) << 3)) * 2);
    const int b_row16 = ((lane >> 4) << 3) + (lane & 7);
    const int b_col8  = ((lane >> 3) & 1) << 3;

    for (int kc = 0; kc < 4; kc++) {
        __syncthreads();
        if (kc + 1 < 4) {
            int buf = (kc + 1) & 1;
            int k0 = (kc + 1) * 64;
            bf16* Ad = smx + buf * BUF;
            bf16* Bd = Ad + 128 * 72;
            #pragma unroll
            for (int i = 0; i < 4; i++) {
                int c = t + i * 256; int row = c >> 3, ch = c & 7;
                cp16(Ad + row * 72 + ch * 8, Ag + (size_t)row * CIN_ + k0 + ch * 8);
            }
            #pragma unroll
            for (int i = 0; i < NT / 32; i++) {
                int c = t + i * 256; int row = c >> 3, ch = c & 7;
                cp16(Bd + row * 72 + ch * 8, Wg + (size_t)row * CIN_ + k0 + ch * 8);
            }
        }
        asm volatile("cp.async.commit_group;\n");
        asm volatile("cp.async.wait_group 1;\n");
        __syncthreads();

        const uint32_t abase = smem_u32(smx + (kc & 1) * BUF);
        const uint32_t bbase = abase + 128 * 72 * 2;

        #pragma unroll
        for (int ks = 0; ks < 4; ks++) {
            uint32_t a0, a1, a2, a3;
            ldsm4(a0, a1, a2, a3, abase + a_off + ks * 32);
            #pragma unroll
            for (int jp = 0; jp < NT / 16; jp++) {
                uint32_t b0, b1, b2, b3;
                ldsm4(b0, b1, b2, b3,
                      bbase + (uint32_t)(((jp * 16 + b_row16) * 72 + ks * 16 + b_col8) * 2));
                mma16816(acc[2 * jp],     a0, a1, a2, a3, b0, b1);
                mma16816(acc[2 * jp + 1], a0, a1, a2, a3, b2, b3);
            }
        }
    }

    // epilogue: + bias, * scale, bf16 store
    const int r = lane >> 2, qr = lane & 3;
    const size_t grow = (size_t)b * Mper + r0 + w * 16 + r;
    #pragma unroll
    for (int jp = 0; jp < NT / 16; jp++) {
        #pragma unroll
        for (int h = 0; h < 2; h++) {
            int col = n0 + jp * 16 + h * 8 + qr * 2;
            float b0f = __ldg(bias + col), b1f = __ldg(bias + col + 1);
            float* c = acc[2 * jp + h];
            uint32_t lo = bf2u((c[0] + b0f) * scale, (c[1] + b1f) * scale);
            uint32_t hi = bf2u((c[2] + b0f) * scale, (c[3] + b1f) * scale);
            *(uint32_t*)(Y + grow * Ntot + col)       = lo;
            *(uint32_t*)(Y + (grow + 8) * Ntot + col) = hi;
        }
    }
}

// ---------------------------------------------------------------------------
// Keep-row passthrough (fp32, exact)
// ---------------------------------------------------------------------------
__global__ void copy_keep(const float4* __restrict__ f, float4* __restrict__ o)
{
    const int per = NK_ * (COUT_ / 4);
    const size_t total = (size_t)B_ * per;
    for (size_t i = blockIdx.x * (size_t)blockDim.x + threadIdx.x; i < total;
         i += (size_t)gridDim.x * blockDim.x) {
        size_t b = i / per;
        size_t r = i - b * per;
        size_t idx = ((size_t)b * T_ + NF_) * (COUT_ / 4) + r;
        o[idx] = f[idx];
    }
}

// ---------------------------------------------------------------------------
// Flash attention (bf16 mma.sync): CTA = 128 fill rows, Bc = 64 keys/tile.
// ---------------------------------------------------------------------------
#define QS_OFF   0
#define KS_OFF   9216
#define VS_OFF   18432
#define ATTN_SMEM_BYTES (104448)

__global__ __launch_bounds__(256) void attn_kernel(
    const bf16* __restrict__ Q, const bf16* __restrict__ K,
    const bf16* __restrict__ V, float* __restrict__ out)
{
    extern __shared__ bf16 smx[];
    bf16* Qs  = smx + QS_OFF;
    bf16* Ksb = smx + KS_OFF;
    bf16* Vsb = smx + VS_OFF;

    const int t = threadIdx.x;
    const int w = t >> 5, lane = t & 31;
    const int b = blockIdx.y, mt = blockIdx.x;

    const bf16* Qg = Q + ((size_t)b * NF_ + mt * 128) * 64;
    const bf16* Kg = K + (size_t)b * NK_ * 64;
    const bf16* Vg = V + (size_t)b * NK_ * 256;

    #pragma unroll
    for (int i = 0; i < 4; i++) {
        int c = t + i * 256;
        int row = c >> 3, ch = c & 7;
        cp16(Qs + row * 72 + ch * 8, Qg + row * 64 + ch * 8);
    }
    asm volatile("cp.async.commit_group;\n");

    #pragma unroll
    for (int i = 0; i < 2; i++) {
        int c = t + i * 256; int row = c >> 3, ch = c & 7;
        cp16(Ksb + row * 72 + ch * 8, Kg + row * 64 + ch * 8);
    }
    #pragma unroll
    for (int i = 0; i < 8; i++) {
        int c = t + i * 256; int row = c >> 5, ch = c & 31;
        cp16(Vsb + row * 264 + ch * 8, Vg + row * 256 + ch * 8);
    }
    asm volatile("cp.async.commit_group;\n");

    float o[32][4];
    #pragma unroll
    for (int n = 0; n < 32; n++) { o[n][0]=0.f; o[n][1]=0.f; o[n][2]=0.f; o[n][3]=0.f; }
    float m0 = -1e30f, m1 = -1e30f, l0 = 0.f, l1 = 0.f;

    const uint32_t qaddr = smem_u32(Qs + (w * 16 + (lane & 15)) * 72 + ((lane >> 4) << 3));
    const int k_row16 = ((lane >> 4) << 3) + (lane & 7);
    const int k_col8  = ((lane >> 3) & 1) << 3;
    const int v_row   = lane & 15;
    const int v_col8  = (lane >> 4) << 3;

    for (int kt = 0; kt < 64; kt++) {
        __syncthreads();
        if (kt + 1 < 64) {
            int buf = (kt + 1) & 1;
            const bf16* Kt = Kg + (size_t)(kt + 1) * 64 * 64;
            const bf16* Vt = Vg + (size_t)(kt + 1) * 64 * 256;
            bf16* Kd = Ksb + buf * 4608;
            bf16* Vd = Vsb + buf * 16896;
            #pragma unroll
            for (int i = 0; i < 2; i++) {
                int c = t + i * 256; int row = c >> 3, ch = c & 7;
                cp16(Kd + row * 72 + ch * 8, Kt + row * 64 + ch * 8);
            }
            #pragma unroll
            for (int i = 0; i < 8; i++) {
                int c = t + i * 256; int row = c >> 5, ch = c & 31;
                cp16(Vd + row * 264 + ch * 8, Vt + row * 256 + ch * 8);
            }
        }
        asm volatile("cp.async.commit_group;\n");
        asm volatile("cp.async.wait_group 1;\n");
        __syncthreads();

        const int cur = kt & 1;
        const uint32_t kbase = smem_u32(Ksb + cur * 4608);
        const uint32_t vbase = smem_u32(Vsb + cur * 16896);

        float s[8][4];
        #pragma unroll
        for (int j = 0; j < 8; j++) { s[j][0]=0.f; s[j][1]=0.f; s[j][2]=0.f; s[j][3]=0.f; }
        #pragma unroll
        for (int ks = 0; ks < 4; ks++) {
            uint32_t a0, a1, a2, a3;
            ldsm4(a0, a1, a2, a3, qaddr + ks * 32);
            #pragma unroll
            for (int jp = 0; jp < 4; jp++) {
                uint32_t b0, b1, b2, b3;
                ldsm4(b0, b1, b2, b3,
                      kbase + (uint32_t)(((16 * jp + k_row16) * 72 + ks * 16 + k_col8) * 2));
                mma16816(s[2 * jp],     a0, a1, a2, a3, b0, b1);
                mma16816(s[2 * jp + 1], a0, a1, a2, a3, b2, b3);
            }
        }

        float mx0 = -1e30f, mx1 = -1e30f;
        #pragma unroll
        for (int j = 0; j < 8; j++) {
            mx0 = fmaxf(mx0, fmaxf(s[j][0], s[j][1]));
            mx1 = fmaxf(mx1, fmaxf(s[j][2], s[j][3]));
        }
        mx0 = fmaxf(mx0, __shfl_xor_sync(0xffffffffu, mx0, 1));
        mx0 = fmaxf(mx0, __shfl_xor_sync(0xffffffffu, mx0, 2));
        mx1 = fmaxf(mx1, __shfl_xor_sync(0xffffffffu, mx1, 1));
        mx1 = fmaxf(mx1, __shfl_xor_sync(0xffffffffu, mx1, 2));
        float mn0 = fmaxf(m0, mx0), mn1 = fmaxf(m1, mx1);
        float c0 = __expf(m0 - mn0), c1 = __expf(m1 - mn1);
        m0 = mn0; m1 = mn1;

        float rs0 = 0.f, rs1 = 0.f;
        uint32_t p[16];
        #pragma unroll
        for (int j = 0; j < 8; j++) {
            float p0 = __expf(s[j][0] - mn0), p1 = __expf(s[j][1] - mn0);
            float p2 = __expf(s[j][2] - mn1), p3 = __expf(s[j][3] - mn1);
            rs0 += p0 + p1; rs1 += p2 + p3;
            p[2 * j]     = bf2u(p0, p1);
            p[2 * j + 1] = bf2u(p2, p3);
        }
        rs0 += __shfl_xor_sync(0xffffffffu, rs0, 1);
        rs0 += __shfl_xor_sync(0xffffffffu, rs0, 2);
        rs1 += __shfl_xor_sync(0xffffffffu, rs1, 1);
        rs1 += __shfl_xor_sync(0xffffffffu, rs1, 2);
        l0 = l0 * c0 + rs0;
        l1 = l1 * c1 + rs1;

        #pragma unroll
        for (int n = 0; n < 32; n++) {
            o[n][0] *= c0; o[n][1] *= c0; o[n][2] *= c1; o[n][3] *= c1;
        }

        #pragma unroll
        for (int kf = 0; kf < 4; kf++) {
            uint32_t pa0 = p[4 * kf + 0], pa1 = p[4 * kf + 1];
            uint32_t pa2 = p[4 * kf + 2], pa3 = p[4 * kf + 3];
            #pragma unroll
            for (int np = 0; np < 16; np++) {
                uint32_t b0, b1, b2, b3;
                ldsm4t(b0, b1, b2, b3,
                       vbase + (uint32_t)(((kf * 16 + v_row) * 264 + np * 16 + v_col8) * 2));
                mma16816(o[2 * np],     pa0, pa1, pa2, pa3, b0, b1);
                mma16816(o[2 * np + 1], pa0, pa1, pa2, pa3, b2, b3);
            }
        }
    }

    const float inv0 = 1.f / l0, inv1 = 1.f / l1;
    const int r = lane >> 2, qr = lane & 3;
    const size_t row0 = (size_t)b * T_ + mt * 128 + w * 16 + r;
    float* o0 = out + row0 * 256 + qr * 2;
    float* o1 = out + (row0 + 8) * 256 + qr * 2;
    #pragma unroll
    for (int n = 0; n < 32; n++) {
        *(float2*)(o0 + n * 8) = make_float2(o[n][0] * inv0, o[n][1] * inv0);
        *(float2*)(o1 + n * 8) = make_float2(o[n][2] * inv1, o[n][3] * inv1);
    }
}

// ---------------------------------------------------------------------------
extern "C" void kernel_launch(void* const* d_in, const int* in_sizes, int n_in,
                              void* d_out, int out_size)
{
    (void)in_sizes; (void)n_in; (void)out_size;
    const float* features = (const float*)d_in[0];
    const float* Wq = (const float*)d_in[2];
    const float* bq = (const float*)d_in[3];
    const float* Wk = (const float*)d_in[4];
    const float* bk = (const float*)d_in[5];
    const float* Wv = (const float*)d_in[6];
    const float* bv = (const float*)d_in[7];
    float* out = (float*)d_out;

    bf16 *qp, *kp, *vp, *fb, *wq, *wk, *wv;
    cudaGetSymbolAddress((void**)&qp, g_Q);
    cudaGetSymbolAddress((void**)&kp, g_K);
    cudaGetSymbolAddress((void**)&vp, g_V);
    cudaGetSymbolAddress((void**)&fb, g_Fb);
    cudaGetSymbolAddress((void**)&wq, g_Wq);
    cudaGetSymbolAddress((void**)&wk, g_Wk);
    cudaGetSymbolAddress((void**)&wv, g_Wv);

    // bf16 conversions
    f2bf<<<1024, 256>>>((const float4*)features, (uint2*)fb, (long)B_ * T_ * CIN_ / 4);
    f2bf<<<16, 256>>>((const float4*)Wq, (uint2*)wq, CKQ_ * CIN_ / 4);
    f2bf<<<16, 256>>>((const float4*)Wk, (uint2*)wk, CKQ_ * CIN_ / 4);
    f2bf<<<64, 256>>>((const float4*)Wv, (uint2*)wv, COUT_ * CIN_ / 4);

    // Tensor-core projections (Q prescaled by 0.125)
    const int smem64  = 2 * (128 * 72 + 64 * 72) * 2;
    const int smem128 = 2 * (128 * 72 + 128 * 72) * 2;
    cudaFuncSetAttribute(proj_mma<64>, cudaFuncAttributeMaxDynamicSharedMemorySize, smem64);
    cudaFuncSetAttribute(proj_mma<128>, cudaFuncAttributeMaxDynamicSharedMemorySize, smem128);
    proj_mma<64><<<dim3((B_ * NF_) / 128, 1), 256, smem64>>>(fb, wq, bq, qp, NF_, 0, CKQ_, 0.125f);
    proj_mma<64><<<dim3((B_ * NK_) / 128, 1), 256, smem64>>>(fb, wk, bk, kp, NK_, NF_, CKQ_, 1.f);
    proj_mma<128><<<dim3((B_ * NK_) / 128, 2), 256, smem128>>>(fb, wv, bv, vp, NK_, NF_, COUT_, 1.f);

    // Passthrough of keep rows
    copy_keep<<<2048, 256>>>((const float4*)features, (float4*)out);

    // Flash attention over fill rows
    cudaFuncSetAttribute(attn_kernel, cudaFuncAttributeMaxDynamicSharedMemorySize,
                         ATTN_SMEM_BYTES);
    attn_kernel<<<dim3(NF_ / 128, B_), 256, ATTN_SMEM_BYTES>>>(qp, kp, vp, out);
}